// round 3
// baseline (speedup 1.0000x reference)
#include <cuda_runtime.h>
#include <math.h>

#define BSZ   16384
#define INDIM 10
#define HDIM  1024
#define SIXH  (6 * HDIM)
#define GD_ITERS 7
#define GD_LR 0.001f
#define BH ((size_t)BSZ * HDIM)

// Scratch (static device globals: no allocations allowed)
__device__ __align__(16) float g_R[(size_t)6 * BSZ * HDIM];  // f,i,ct,o,c_new,h_std blocks
__device__ float g_theta[SIXH];
__device__ float g_grad[SIXH];
__device__ int   g_argmax;

__device__ __forceinline__ float sigmoid_f(float v) { return 1.0f / (1.0f + expf(-v)); }

// ---------------------------------------------------------------------------
// Kernel 1: fused gate GEMM + activations.
// Block tile: 64 rows (b) x 64 cols (h) x 4 gates. 256 threads, each thread
// computes a 4x4 micro-tile for all 4 gates (64 accumulators).
// pre_g = hidden @ U_g^T  (main K=1024 loop)  +  x @ W_g^T + b_g  (epilogue).
// Epilogue computes f,i,ct,o,c_new,h_std and writes the 6 r_t blocks + c_new
// into out[BH:2BH].
// ---------------------------------------------------------------------------
__global__ __launch_bounds__(256) void k_gates(
    const float* __restrict__ x, const float* __restrict__ hidden, const float* __restrict__ cin,
    const float* __restrict__ Wf, const float* __restrict__ bf, const float* __restrict__ Uf,
    const float* __restrict__ Wi, const float* __restrict__ bi, const float* __restrict__ Ui,
    const float* __restrict__ Wc, const float* __restrict__ bc, const float* __restrict__ Uc,
    const float* __restrict__ Wo, const float* __restrict__ bo, const float* __restrict__ Uo,
    float* __restrict__ out)
{
    __shared__ float As[64][17];                       // hidden tile [b][k], padded
    __shared__ __align__(16) float Bs[4][16][64];      // U tiles [gate][k][h]
    __shared__ float Xs[64][INDIM];                    // x tile [b][j]
    __shared__ float Ws[4][64][INDIM];                 // W tiles [gate][h][j]

    const int t  = threadIdx.x;
    const int b0 = blockIdx.x * 64;
    const int h0 = blockIdx.y * 64;

    const float* Up[4] = {Uf, Ui, Uc, Uo};

    // Preload Xs and Ws (consumed only in the epilogue; covered by 1st barrier)
    for (int idx = t; idx < 64 * INDIM; idx += 256) {
        int r = idx / INDIM, j = idx % INDIM;
        Xs[r][j] = x[(size_t)(b0 + r) * INDIM + j];
    }
    for (int idx = t; idx < 64 * INDIM; idx += 256) {
        int r = idx / INDIM, j = idx % INDIM;
        Ws[0][r][j] = Wf[(size_t)(h0 + r) * INDIM + j];
        Ws[1][r][j] = Wi[(size_t)(h0 + r) * INDIM + j];
        Ws[2][r][j] = Wc[(size_t)(h0 + r) * INDIM + j];
        Ws[3][r][j] = Wo[(size_t)(h0 + r) * INDIM + j];
    }

    float acc[4][4][4];   // [gate][bi][hj]
    #pragma unroll
    for (int g = 0; g < 4; g++)
        #pragma unroll
        for (int a = 0; a < 4; a++)
            #pragma unroll
            for (int b = 0; b < 4; b++) acc[g][a][b] = 0.0f;

    const int ty = t >> 4;      // 0..15 -> b rows ty*4..
    const int tx = t & 15;      // 0..15 -> h cols tx*4..
    const int lr = t >> 2;      // 0..63 loader row
    const int lq = t & 3;       // 0..3  loader k-quad

    for (int kt = 0; kt < HDIM; kt += 16) {
        // Load hidden tile
        {
            const float4 av = *(const float4*)(hidden + (size_t)(b0 + lr) * HDIM + kt + lq * 4);
            As[lr][lq * 4 + 0] = av.x; As[lr][lq * 4 + 1] = av.y;
            As[lr][lq * 4 + 2] = av.z; As[lr][lq * 4 + 3] = av.w;
        }
        // Load 4 U tiles (transposed to [k][h])
        #pragma unroll
        for (int g = 0; g < 4; g++) {
            const float4 uv = *(const float4*)(Up[g] + (size_t)(h0 + lr) * HDIM + kt + lq * 4);
            Bs[g][lq * 4 + 0][lr] = uv.x; Bs[g][lq * 4 + 1][lr] = uv.y;
            Bs[g][lq * 4 + 2][lr] = uv.z; Bs[g][lq * 4 + 3][lr] = uv.w;
        }
        __syncthreads();

        #pragma unroll
        for (int k = 0; k < 16; k++) {
            float a0 = As[ty * 4 + 0][k];
            float a1 = As[ty * 4 + 1][k];
            float a2 = As[ty * 4 + 2][k];
            float a3 = As[ty * 4 + 3][k];
            #pragma unroll
            for (int g = 0; g < 4; g++) {
                const float4 bv = *(const float4*)&Bs[g][k][tx * 4];
                acc[g][0][0] += a0 * bv.x; acc[g][0][1] += a0 * bv.y;
                acc[g][0][2] += a0 * bv.z; acc[g][0][3] += a0 * bv.w;
                acc[g][1][0] += a1 * bv.x; acc[g][1][1] += a1 * bv.y;
                acc[g][1][2] += a1 * bv.z; acc[g][1][3] += a1 * bv.w;
                acc[g][2][0] += a2 * bv.x; acc[g][2][1] += a2 * bv.y;
                acc[g][2][2] += a2 * bv.z; acc[g][2][3] += a2 * bv.w;
                acc[g][3][0] += a3 * bv.x; acc[g][3][1] += a3 * bv.y;
                acc[g][3][2] += a3 * bv.z; acc[g][3][3] += a3 * bv.w;
            }
        }
        __syncthreads();
    }

    // Epilogue
    const int gh0 = h0 + tx * 4;
    float bfa[4], bia[4], bca[4], boa[4];
    #pragma unroll
    for (int j = 0; j < 4; j++) {
        bfa[j] = bf[gh0 + j]; bia[j] = bi[gh0 + j];
        bca[j] = bc[gh0 + j]; boa[j] = bo[gh0 + j];
    }

    #pragma unroll
    for (int biR = 0; biR < 4; biR++) {
        const int bl  = ty * 4 + biR;
        const int row = b0 + bl;

        float px[4][4];
        #pragma unroll
        for (int g = 0; g < 4; g++)
            #pragma unroll
            for (int j = 0; j < 4; j++) px[g][j] = acc[g][biR][j];

        #pragma unroll
        for (int m = 0; m < INDIM; m++) {
            const float xv = Xs[bl][m];
            #pragma unroll
            for (int g = 0; g < 4; g++)
                #pragma unroll
                for (int j = 0; j < 4; j++)
                    px[g][j] += xv * Ws[g][tx * 4 + j][m];
        }

        const float4 cold = *(const float4*)(cin + (size_t)row * HDIM + gh0);
        const float cv[4] = {cold.x, cold.y, cold.z, cold.w};

        float fo[4], io[4], cto[4], oo[4], cno[4], hso[4];
        #pragma unroll
        for (int j = 0; j < 4; j++) {
            const float f  = sigmoid_f(px[0][j] + bfa[j]);
            const float ii = sigmoid_f(px[1][j] + bia[j]);
            const float ct = tanhf(px[2][j] + bca[j]);
            const float o  = sigmoid_f(px[3][j] + boa[j]);
            const float cn = f * cv[j] + ii * ct;
            const float hs = o * tanhf(cn);
            fo[j] = f; io[j] = ii; cto[j] = ct; oo[j] = o; cno[j] = cn; hso[j] = hs;
        }

        const size_t ob = (size_t)row * HDIM + gh0;
        *(float4*)(g_R + 0 * BH + ob) = make_float4(fo[0], fo[1], fo[2], fo[3]);
        *(float4*)(g_R + 1 * BH + ob) = make_float4(io[0], io[1], io[2], io[3]);
        *(float4*)(g_R + 2 * BH + ob) = make_float4(cto[0], cto[1], cto[2], cto[3]);
        *(float4*)(g_R + 3 * BH + ob) = make_float4(oo[0], oo[1], oo[2], oo[3]);
        *(float4*)(g_R + 4 * BH + ob) = make_float4(cno[0], cno[1], cno[2], cno[3]);
        *(float4*)(g_R + 5 * BH + ob) = make_float4(hso[0], hso[1], hso[2], hso[3]);
        *(float4*)(out + BH + ob)     = make_float4(cno[0], cno[1], cno[2], cno[3]);
    }
}

// ---------------------------------------------------------------------------
// Zero theta + grad (must re-run every launch: graph replays must be idempotent)
// ---------------------------------------------------------------------------
__global__ void k_zero() {
    const int i = blockIdx.x * blockDim.x + threadIdx.x;
    if (i < SIXH) { g_theta[i] = 0.0f; g_grad[i] = 0.0f; }
}

// ---------------------------------------------------------------------------
// One GD iteration, single pass over R:
//   per row: err = dot(r_row, theta) - mp[row]; grad += err * r_row
// Row values live in 24 registers per thread (col c = t + 256*j, coalesced);
// per-thread grad lives in 24 registers, flushed once via atomics.
// theta cached in 24KB shared.
// ---------------------------------------------------------------------------
__global__ __launch_bounds__(256) void k_gd(const float* __restrict__ mp) {
    __shared__ float sth[SIXH];
    __shared__ float red[8];
    __shared__ float serr;

    const int t = threadIdx.x;
    for (int i = t; i < SIXH; i += 256) sth[i] = g_theta[i];
    __syncthreads();

    float gacc[24];
    #pragma unroll
    for (int j = 0; j < 24; j++) gacc[j] = 0.0f;

    float vals[24];
    for (int row = blockIdx.x; row < BSZ; row += gridDim.x) {
        const float* rowp = g_R + (size_t)row * HDIM;
        float s = 0.0f;
        #pragma unroll
        for (int j = 0; j < 24; j++) {
            const int cidx = t + 256 * j;
            const int blk = cidx >> 10;
            const int off = cidx & 1023;
            const float v = rowp[(size_t)blk * BH + off];
            vals[j] = v;
            s += v * sth[cidx];
        }
        #pragma unroll
        for (int o = 16; o > 0; o >>= 1) s += __shfl_xor_sync(0xffffffffu, s, o);
        if ((t & 31) == 0) red[t >> 5] = s;
        __syncthreads();
        if (t == 0) {
            float e = red[0];
            #pragma unroll
            for (int w = 1; w < 8; w++) e += red[w];
            serr = e - mp[row];
        }
        __syncthreads();
        const float err = serr;
        #pragma unroll
        for (int j = 0; j < 24; j++) gacc[j] += err * vals[j];
    }

    #pragma unroll
    for (int j = 0; j < 24; j++) atomicAdd(&g_grad[t + 256 * j], gacc[j]);
}

// theta -= lr * 2/B * grad ; grad = 0 for next iteration
__global__ void k_update() {
    const int i = blockIdx.x * blockDim.x + threadIdx.x;
    if (i < SIXH) {
        g_theta[i] -= (2.0f * GD_LR / (float)BSZ) * g_grad[i];
        g_grad[i] = 0.0f;
    }
}

// importance = mean |theta| per 1024-block; argmax (first max wins, like jnp.argmax)
__global__ void k_argmax() {
    __shared__ float ssum[6];
    const int t = threadIdx.x;
    if (t < 6) ssum[t] = 0.0f;
    __syncthreads();
    for (int blk = 0; blk < 6; blk++) {
        float p = 0.0f;
        for (int i = t; i < HDIM; i += 256) p += fabsf(g_theta[blk * HDIM + i]);
        #pragma unroll
        for (int o = 16; o > 0; o >>= 1) p += __shfl_xor_sync(0xffffffffu, p, o);
        if ((t & 31) == 0) atomicAdd(&ssum[blk], p);
    }
    __syncthreads();
    if (t == 0) {
        int best = 0; float bv = ssum[0];
        #pragma unroll
        for (int b = 1; b < 6; b++) if (ssum[b] > bv) { bv = ssum[b]; best = b; }
        g_argmax = best;
    }
}

// h_new = R[argmax block] -> out[0:BH)
__global__ void k_copy(float* __restrict__ out) {
    const size_t i = ((size_t)blockIdx.x * 256 + threadIdx.x) * 4;
    const int m = g_argmax;
    const float4 v = *(const float4*)(g_R + (size_t)m * BH + i);
    *(float4*)(out + i) = v;
}

// ---------------------------------------------------------------------------
extern "C" void kernel_launch(void* const* d_in, const int* in_sizes, int n_in,
                              void* d_out, int out_size)
{
    const float* x      = (const float*)d_in[0];
    const float* hidden = (const float*)d_in[1];
    const float* cin    = (const float*)d_in[2];
    const float* mp     = (const float*)d_in[3];
    const float* Wf     = (const float*)d_in[4];
    const float* bf     = (const float*)d_in[5];
    const float* Uf     = (const float*)d_in[6];
    const float* Wi     = (const float*)d_in[7];
    const float* bi     = (const float*)d_in[8];
    const float* Ui     = (const float*)d_in[9];
    const float* Wc     = (const float*)d_in[10];
    const float* bc     = (const float*)d_in[11];
    const float* Uc     = (const float*)d_in[12];
    const float* Wo     = (const float*)d_in[13];
    const float* bo     = (const float*)d_in[14];
    const float* Uo     = (const float*)d_in[15];
    float* out = (float*)d_out;

    dim3 gg(BSZ / 64, HDIM / 64);
    k_gates<<<gg, 256>>>(x, hidden, cin,
                         Wf, bf, Uf, Wi, bi, Ui, Wc, bc, Uc, Wo, bo, Uo, out);
    k_zero<<<(SIXH + 255) / 256, 256>>>();
    for (int it = 0; it < GD_ITERS; it++) {
        k_gd<<<592, 256>>>(mp);
        k_update<<<(SIXH + 255) / 256, 256>>>();
    }
    k_argmax<<<1, 256>>>();
    k_copy<<<(int)(BH / (256 * 4)), 256>>>(out);
}

// round 13
// speedup vs baseline: 2.3713x; 2.3713x over previous
#include <cuda_runtime.h>
#include <cuda_bf16.h>
#include <math.h>

constexpr int    BSZ      = 16384;
constexpr int    INDIM    = 10;
constexpr int    HDIM     = 1024;
constexpr int    SIXH     = 6144;
constexpr int    GD_ITERS = 7;
constexpr float  GD_LR    = 0.001f;
constexpr size_t BH       = 16777216ULL;   // BSZ * HDIM
constexpr int    KPAD     = 1056;          // 1024 + 32 augmented K cols
constexpr int    NCH      = 33;            // K chunks of 32
constexpr int    NROW4    = 4096;          // 4 * HDIM output cols
constexpr unsigned ASTRIDE = 80u;          // smem row stride (64B data + 16B pad)
constexpr unsigned A_HALF  = 10240u;       // 128 rows * 80
constexpr unsigned B_HALF  = 20480u;       // 256 rows * 80
constexpr unsigned STAGE   = 61440u;       // Ah+Al+Bh+Bl
constexpr int    SMEM_NEED = 122880;       // 2 stages

// ------------------ static device scratch (no allocations) ------------------
__device__ __align__(16) float g_R[6 * BH];                        // r_t blocks
__device__ __align__(16) float g_P[(size_t)BSZ * NROW4];           // pre-activations
__device__ __align__(16) __nv_bfloat16 g_Ah[(size_t)BSZ * KPAD];   // A' hi
__device__ __align__(16) __nv_bfloat16 g_Al[(size_t)BSZ * KPAD];   // A' lo
__device__ __align__(16) __nv_bfloat16 g_Bh[(size_t)NROW4 * KPAD]; // B' hi
__device__ __align__(16) __nv_bfloat16 g_Bl[(size_t)NROW4 * KPAD]; // B' lo
__device__ float g_theta[SIXH];
__device__ float g_grad[SIXH];
__device__ int g_argmax;

__device__ __forceinline__ float sigmoid_f(float v) { return 1.0f / (1.0f + expf(-v)); }

// ------------------------------ PTX helpers ---------------------------------
__device__ __forceinline__ unsigned smem_u32(const void* p) {
    return (unsigned)__cvta_generic_to_shared(p);
}
__device__ __forceinline__ void cp16(unsigned dst, const void* src) {
    asm volatile("cp.async.cg.shared.global [%0], [%1], 16;" :: "r"(dst), "l"(src));
}
__device__ __forceinline__ void cp_commit() {
    asm volatile("cp.async.commit_group;" ::: "memory");
}
__device__ __forceinline__ void cp_wait1() {
    asm volatile("cp.async.wait_group 1;" ::: "memory");
}
__device__ __forceinline__ void cp_wait0() {
    asm volatile("cp.async.wait_group 0;" ::: "memory");
}
__device__ __forceinline__ unsigned lds32(unsigned a) {
    unsigned v;
    asm volatile("ld.shared.b32 %0, [%1];" : "=r"(v) : "r"(a));
    return v;
}
__device__ __forceinline__ void mma16816(float* d, const unsigned* a,
                                         unsigned b0, unsigned b1) {
    asm volatile(
        "mma.sync.aligned.m16n8k16.row.col.f32.bf16.bf16.f32 "
        "{%0,%1,%2,%3}, {%4,%5,%6,%7}, {%8,%9}, {%0,%1,%2,%3};"
        : "+f"(d[0]), "+f"(d[1]), "+f"(d[2]), "+f"(d[3])
        : "r"(a[0]), "r"(a[1]), "r"(a[2]), "r"(a[3]), "r"(b0), "r"(b1));
}

// ------------------------------ prep kernels --------------------------------
__device__ __forceinline__ void split_store4(const float* srcp, __nv_bfloat16* dh,
                                             __nv_bfloat16* dl, size_t doff, size_t s4) {
    float4 v = ((const float4*)srcp)[s4];
    float a[4];
    a[0] = v.x; a[1] = v.y; a[2] = v.z; a[3] = v.w;
    __nv_bfloat16 hi[4];
    __nv_bfloat16 lo[4];
    for (int k = 0; k < 4; k++) {
        hi[k] = __float2bfloat16(a[k]);
        lo[k] = __float2bfloat16(a[k] - __bfloat162float(hi[k]));
    }
    *(uint2*)(dh + doff) = *(uint2*)hi;
    *(uint2*)(dl + doff) = *(uint2*)lo;
}

__global__ void k_prep_h(const float* __restrict__ hidden) {
    size_t i = (size_t)blockIdx.x * blockDim.x + threadIdx.x;
    if (i >= (size_t)BSZ * HDIM / 4) return;
    size_t row = i >> 8;
    size_t q = i & 255;
    split_store4(hidden, g_Ah, g_Al, row * KPAD + q * 4, i);
}

__global__ void k_prep_u(const float* __restrict__ Uf, const float* __restrict__ Ui,
                         const float* __restrict__ Uc, const float* __restrict__ Uo) {
    size_t i = (size_t)blockIdx.x * blockDim.x + threadIdx.x;
    if (i >= (size_t)NROW4 * HDIM / 4) return;
    size_t n = i >> 8;
    size_t q = i & 255;
    int g = (int)(n >> 10);
    size_t h = n & 1023;
    const float* Up;
    if (g == 0) Up = Uf;
    else if (g == 1) Up = Ui;
    else if (g == 2) Up = Uc;
    else Up = Uo;
    split_store4(Up, g_Bh, g_Bl, n * KPAD + q * 4, h * 256 + q);
}

__global__ void k_prep_aug(const float* __restrict__ x,
                           const float* __restrict__ Wf, const float* __restrict__ Wi,
                           const float* __restrict__ Wc, const float* __restrict__ Wo,
                           const float* __restrict__ bf, const float* __restrict__ bi,
                           const float* __restrict__ bc, const float* __restrict__ bo) {
    int r = blockIdx.x * blockDim.x + threadIdx.x;
    float v[32];
    for (int m = 0; m < 32; m++) v[m] = 0.0f;
    __nv_bfloat16* dh;
    __nv_bfloat16* dl;
    if (r < BSZ) {
        for (int m = 0; m < INDIM; m++) v[m] = x[r * INDIM + m];
        v[10] = 1.0f;
        dh = g_Ah + (size_t)r * KPAD + 1024;
        dl = g_Al + (size_t)r * KPAD + 1024;
    } else if (r < BSZ + NROW4) {
        int n = r - BSZ;
        int g = n >> 10;
        int h = n & 1023;
        const float* Wp;
        const float* bp;
        if (g == 0) { Wp = Wf; bp = bf; }
        else if (g == 1) { Wp = Wi; bp = bi; }
        else if (g == 2) { Wp = Wc; bp = bc; }
        else { Wp = Wo; bp = bo; }
        for (int m = 0; m < INDIM; m++) v[m] = Wp[h * INDIM + m];
        v[10] = bp[h];
        dh = g_Bh + (size_t)n * KPAD + 1024;
        dl = g_Bl + (size_t)n * KPAD + 1024;
    } else {
        return;
    }
    for (int k = 0; k < 32; k++) {
        __nv_bfloat16 hv = __float2bfloat16(v[k]);
        __nv_bfloat16 lv = __float2bfloat16(v[k] - __bfloat162float(hv));
        dh[k] = hv;
        dl[k] = lv;
    }
}

// --------------------------- gates GEMM (mma.sync) --------------------------
// CTA: 128 rows x 256 cols, 512 threads = 16 warps as 4(m) x 4(n).
// Warp: m32 x n64 -> acc[2 msub][8 nfrag][4]. K chunks of 32, double buffered.
// Smem stage: Ah[128x80] Al[128x80] Bh[256x80] Bl[256x80], 80B row stride
// (64B data + 16B pad -> conflict-free b32 fragment loads).

__device__ __forceinline__ void load_chunk(int c, unsigned stg, int b0, int n0, int t) {
    int k0 = c * 32;
    for (int i = 0; i < 6; i++) {
        int u = t + 512 * i;
        if (u < 1024) {
            int half = u >> 9;
            int rr = (u >> 2) & 127;
            int seg = u & 3;
            const __nv_bfloat16* base = (half == 0) ? g_Ah : g_Al;
            const __nv_bfloat16* src = base + (size_t)(b0 + rr) * KPAD + k0 + seg * 8;
            cp16(stg + (unsigned)half * A_HALF + (unsigned)(rr * 80 + seg * 16), src);
        } else {
            int v = u - 1024;
            int half = v >> 10;
            int rr = (v >> 2) & 255;
            int seg = v & 3;
            const __nv_bfloat16* base = (half == 0) ? g_Bh : g_Bl;
            const __nv_bfloat16* src = base + (size_t)(n0 + rr) * KPAD + k0 + seg * 8;
            cp16(stg + 2u * A_HALF + (unsigned)half * B_HALF
                 + (unsigned)(rr * 80 + seg * 16), src);
        }
    }
}

__global__ __launch_bounds__(512) void k_gates_mma() {
    extern __shared__ char smem_raw[];
    unsigned sbase = smem_u32(smem_raw);
    int t = threadIdx.x;
    int b0 = blockIdx.x * 128;
    int n0 = blockIdx.y * 256;
    int w = t >> 5;
    int lane = t & 31;
    int mi = w >> 2;       // 0..3 -> rows mi*32
    int ni = w & 3;        // 0..3 -> cols ni*64
    int gid = lane >> 2;   // 0..7
    int four = lane & 3;   // 0..3

    float acc[2][8][4];
    for (int ms = 0; ms < 2; ms++)
        for (int nf = 0; nf < 8; nf++)
            for (int j = 0; j < 4; j++) acc[ms][nf][j] = 0.0f;

    load_chunk(0, sbase, b0, n0, t);
    cp_commit();

    for (int c = 0; c < NCH; c++) {
        unsigned stg = sbase + (unsigned)(c & 1) * STAGE;
        if (c + 1 < NCH) {
            load_chunk(c + 1, sbase + (unsigned)((c + 1) & 1) * STAGE, b0, n0, t);
            cp_commit();
            cp_wait1();
        } else {
            cp_wait0();
        }
        __syncthreads();

        for (int kk = 0; kk < 2; kk++) {
            // A fragments: hi and lo halves, 2 m16 sub-slabs
            unsigned arow = stg + (unsigned)((mi * 32 + gid) * 80 + kk * 32 + four * 4);
            unsigned ah[2][4];
            unsigned al[2][4];
            for (int ms = 0; ms < 2; ms++) {
                unsigned a0 = arow + (unsigned)(ms * 16 * 80);
                ah[ms][0] = lds32(a0);
                ah[ms][1] = lds32(a0 + 640u);
                ah[ms][2] = lds32(a0 + 16u);
                ah[ms][3] = lds32(a0 + 656u);
                unsigned a1 = a0 + A_HALF;
                al[ms][0] = lds32(a1);
                al[ms][1] = lds32(a1 + 640u);
                al[ms][2] = lds32(a1 + 16u);
                al[ms][3] = lds32(a1 + 656u);
            }
            unsigned bbase = stg + 2u * A_HALF
                           + (unsigned)((ni * 64 + gid) * 80 + kk * 32 + four * 4);
            for (int nf = 0; nf < 8; nf++) {
                unsigned bo = bbase + (unsigned)(nf * 8 * 80);
                unsigned bh0 = lds32(bo);
                unsigned bh1 = lds32(bo + 16u);
                unsigned bl0 = lds32(bo + B_HALF);
                unsigned bl1 = lds32(bo + B_HALF + 16u);
                for (int ms = 0; ms < 2; ms++) {
                    mma16816(acc[ms][nf], ah[ms], bh0, bh1);
                    mma16816(acc[ms][nf], ah[ms], bl0, bl1);
                    mma16816(acc[ms][nf], al[ms], bh0, bh1);
                }
            }
        }
        __syncthreads();
    }

    // store pre-activations
    for (int ms = 0; ms < 2; ms++) {
        for (int nf = 0; nf < 8; nf++) {
            int row = b0 + mi * 32 + ms * 16 + gid;
            int col = n0 + ni * 64 + nf * 8 + four * 2;
            float2 v01;
            v01.x = acc[ms][nf][0];
            v01.y = acc[ms][nf][1];
            *(float2*)(g_P + (size_t)row * NROW4 + col) = v01;
            float2 v23;
            v23.x = acc[ms][nf][2];
            v23.y = acc[ms][nf][3];
            *(float2*)(g_P + (size_t)(row + 8) * NROW4 + col) = v23;
        }
    }
}

// -------------------------- activation epilogue ------------------------------
__global__ __launch_bounds__(256) void k_act(const float* __restrict__ cin,
                                             float* __restrict__ out) {
    size_t q = (size_t)blockIdx.x * blockDim.x + threadIdx.x;
    if (q >= (size_t)BSZ * 256) return;
    size_t row = q >> 8;
    size_t h4 = (q & 255) * 4;
    const float* prow = g_P + row * NROW4;
    float4 pf = *(const float4*)(prow + h4);
    float4 pi = *(const float4*)(prow + 1024 + h4);
    float4 pc = *(const float4*)(prow + 2048 + h4);
    float4 po = *(const float4*)(prow + 3072 + h4);
    float4 cold = *(const float4*)(cin + row * HDIM + h4);

    float fv[4];
    float iv[4];
    float cv[4];
    float ov[4];
    float cnv[4];
    float hsv[4];
    float af[4] = {pf.x, pf.y, pf.z, pf.w};
    float ai[4] = {pi.x, pi.y, pi.z, pi.w};
    float ac[4] = {pc.x, pc.y, pc.z, pc.w};
    float ao[4] = {po.x, po.y, po.z, po.w};
    float cc[4] = {cold.x, cold.y, cold.z, cold.w};
    for (int j = 0; j < 4; j++) {
        float f = sigmoid_f(af[j]);
        float ii = sigmoid_f(ai[j]);
        float ct = tanhf(ac[j]);
        float o = sigmoid_f(ao[j]);
        float cn = f * cc[j] + ii * ct;
        fv[j] = f;
        iv[j] = ii;
        cv[j] = ct;
        ov[j] = o;
        cnv[j] = cn;
        hsv[j] = o * tanhf(cn);
    }
    size_t ob = row * HDIM + h4;
    *(float4*)(g_R + ob) = make_float4(fv[0], fv[1], fv[2], fv[3]);
    *(float4*)(g_R + BH + ob) = make_float4(iv[0], iv[1], iv[2], iv[3]);
    *(float4*)(g_R + 2 * BH + ob) = make_float4(cv[0], cv[1], cv[2], cv[3]);
    *(float4*)(g_R + 3 * BH + ob) = make_float4(ov[0], ov[1], ov[2], ov[3]);
    *(float4*)(g_R + 4 * BH + ob) = make_float4(cnv[0], cnv[1], cnv[2], cnv[3]);
    *(float4*)(g_R + 5 * BH + ob) = make_float4(hsv[0], hsv[1], hsv[2], hsv[3]);
    *(float4*)(out + BH + ob) = make_float4(cnv[0], cnv[1], cnv[2], cnv[3]);
}

// ------------------------------- GD kernels ---------------------------------
__global__ void k_zero() {
    int i = blockIdx.x * blockDim.x + threadIdx.x;
    if (i < SIXH) {
        g_theta[i] = 0.0f;
        g_grad[i] = 0.0f;
    }
}

__global__ __launch_bounds__(256) void k_gd(const float* __restrict__ mp) {
    __shared__ float sth[SIXH];
    __shared__ float red[8];
    __shared__ float serr;

    int t = threadIdx.x;
    for (int i = t; i < SIXH; i += 256) sth[i] = g_theta[i];
    __syncthreads();

    float gacc[24];
    for (int j = 0; j < 24; j++) gacc[j] = 0.0f;

    float vals[24];
    for (int row = blockIdx.x; row < BSZ; row += gridDim.x) {
        const float* rowp = g_R + (size_t)row * HDIM;
        float s = 0.0f;
        for (int j = 0; j < 24; j++) {
            int cidx = t + 256 * j;
            int blk = cidx >> 10;
            int off = cidx & 1023;
            float v = rowp[(size_t)blk * BH + off];
            vals[j] = v;
            s += v * sth[cidx];
        }
        for (int o = 16; o > 0; o >>= 1) s += __shfl_xor_sync(0xffffffffu, s, o);
        if ((t & 31) == 0) red[t >> 5] = s;
        __syncthreads();
        if (t == 0) {
            float e = red[0];
            for (int w = 1; w < 8; w++) e += red[w];
            serr = e - mp[row];
        }
        __syncthreads();
        float err = serr;
        for (int j = 0; j < 24; j++) gacc[j] += err * vals[j];
    }

    for (int j = 0; j < 24; j++) atomicAdd(&g_grad[t + 256 * j], gacc[j]);
}

__global__ void k_update() {
    int i = blockIdx.x * blockDim.x + threadIdx.x;
    if (i < SIXH) {
        g_theta[i] -= (2.0f * GD_LR / (float)BSZ) * g_grad[i];
        g_grad[i] = 0.0f;
    }
}

__global__ void k_argmax() {
    __shared__ float ssum[6];
    int t = threadIdx.x;
    if (t < 6) ssum[t] = 0.0f;
    __syncthreads();
    for (int blk = 0; blk < 6; blk++) {
        float p = 0.0f;
        for (int i = t; i < HDIM; i += 256) p += fabsf(g_theta[blk * HDIM + i]);
        for (int o = 16; o > 0; o >>= 1) p += __shfl_xor_sync(0xffffffffu, p, o);
        if ((t & 31) == 0) atomicAdd(&ssum[blk], p);
    }
    __syncthreads();
    if (t == 0) {
        int best = 0;
        float bv = ssum[0];
        for (int b = 1; b < 6; b++) {
            if (ssum[b] > bv) { bv = ssum[b]; best = b; }
        }
        g_argmax = best;
    }
}

__global__ void k_copy(float* __restrict__ out) {
    size_t i = ((size_t)blockIdx.x * 256 + threadIdx.x) * 4;
    int m = g_argmax;
    *(float4*)(out + i) = *(const float4*)(g_R + (size_t)m * BH + i);
}

// ---------------------------------------------------------------------------
extern "C" void kernel_launch(void* const* d_in, const int* in_sizes, int n_in,
                              void* d_out, int out_size)
{
    const float* x      = (const float*)d_in[0];
    const float* hidden = (const float*)d_in[1];
    const float* cin    = (const float*)d_in[2];
    const float* mp     = (const float*)d_in[3];
    const float* Wf     = (const float*)d_in[4];
    const float* bf     = (const float*)d_in[5];
    const float* Uf     = (const float*)d_in[6];
    const float* Wi     = (const float*)d_in[7];
    const float* bi     = (const float*)d_in[8];
    const float* Ui     = (const float*)d_in[9];
    const float* Wc     = (const float*)d_in[10];
    const float* bc     = (const float*)d_in[11];
    const float* Uc     = (const float*)d_in[12];
    const float* Wo     = (const float*)d_in[13];
    const float* bo     = (const float*)d_in[14];
    const float* Uo     = (const float*)d_in[15];
    float* out = (float*)d_out;

    cudaFuncSetAttribute(k_gates_mma, cudaFuncAttributeMaxDynamicSharedMemorySize,
                         SMEM_NEED);

    k_prep_h<<<BSZ * HDIM / 4 / 256, 256>>>(hidden);
    k_prep_u<<<NROW4 * HDIM / 4 / 256, 256>>>(Uf, Ui, Uc, Uo);
    k_prep_aug<<<(BSZ + NROW4) / 256, 256>>>(x, Wf, Wi, Wc, Wo, bf, bi, bc, bo);

    dim3 gg(BSZ / 128, NROW4 / 256);
    k_gates_mma<<<gg, 512, SMEM_NEED>>>();
    k_act<<<BSZ * 256 / 256, 256>>>(cin, out);

    k_zero<<<(SIXH + 255) / 256, 256>>>();
    for (int it = 0; it < GD_ITERS; it++) {
        k_gd<<<592, 256>>>(mp);
        k_update<<<(SIXH + 255) / 256, 256>>>();
    }
    k_argmax<<<1, 256>>>();
    k_copy<<<(int)(BH / 1024ULL), 256>>>(out);
}

// round 14
// speedup vs baseline: 2.4276x; 1.0238x over previous
#include <cuda_runtime.h>
#include <cuda_bf16.h>
#include <math.h>

constexpr int    BSZ      = 16384;
constexpr int    INDIM    = 10;
constexpr int    HDIM     = 1024;
constexpr int    SIXH     = 6144;
constexpr int    GD_ITERS = 7;
constexpr float  GD_LR    = 0.001f;
constexpr size_t BH       = 16777216ULL;   // BSZ * HDIM
constexpr int    KPAD     = 1056;          // 1024 + 32 augmented K cols
constexpr int    NCH      = 33;            // K chunks of 32
constexpr int    NROW4    = 4096;          // 4 * HDIM output cols
constexpr unsigned A_HALF  = 10240u;       // 128 rows * 80
constexpr unsigned B_HALF  = 20480u;       // 256 rows * 80
constexpr unsigned STAGE   = 61440u;       // Ah+Al+Bh+Bl
constexpr int    SMEM_NEED = 122880;       // 2 stages

// ------------------ static device scratch (no allocations) ------------------
__device__ __align__(16) float g_R[6 * BH];                        // r_t blocks fp32
__device__ __align__(16) __nv_bfloat16 g_Rb[6 * BH];               // r_t blocks bf16 (GD)
__device__ __align__(16) float g_P[(size_t)BSZ * NROW4];           // pre-activations
__device__ __align__(16) __nv_bfloat16 g_Ah[(size_t)BSZ * KPAD];   // A' hi
__device__ __align__(16) __nv_bfloat16 g_Al[(size_t)BSZ * KPAD];   // A' lo
__device__ __align__(16) __nv_bfloat16 g_Bh[(size_t)NROW4 * KPAD]; // B' hi
__device__ __align__(16) __nv_bfloat16 g_Bl[(size_t)NROW4 * KPAD]; // B' lo
__device__ float g_theta[SIXH];
__device__ float g_grad[SIXH];
__device__ int g_argmax;

__device__ __forceinline__ float sigmoid_f(float v) { return 1.0f / (1.0f + expf(-v)); }

// ------------------------------ PTX helpers ---------------------------------
__device__ __forceinline__ unsigned smem_u32(const void* p) {
    return (unsigned)__cvta_generic_to_shared(p);
}
__device__ __forceinline__ void cp16(unsigned dst, const void* src) {
    asm volatile("cp.async.cg.shared.global [%0], [%1], 16;" :: "r"(dst), "l"(src));
}
__device__ __forceinline__ void cp_commit() {
    asm volatile("cp.async.commit_group;" ::: "memory");
}
__device__ __forceinline__ void cp_wait1() {
    asm volatile("cp.async.wait_group 1;" ::: "memory");
}
__device__ __forceinline__ void cp_wait0() {
    asm volatile("cp.async.wait_group 0;" ::: "memory");
}
__device__ __forceinline__ void ldm4(unsigned* r, unsigned addr) {
    asm volatile(
        "ldmatrix.sync.aligned.m8n8.x4.shared.b16 {%0,%1,%2,%3}, [%4];"
        : "=r"(r[0]), "=r"(r[1]), "=r"(r[2]), "=r"(r[3]) : "r"(addr));
}
__device__ __forceinline__ void mma16816(float* d, const unsigned* a,
                                         unsigned b0, unsigned b1) {
    asm volatile(
        "mma.sync.aligned.m16n8k16.row.col.f32.bf16.bf16.f32 "
        "{%0,%1,%2,%3}, {%4,%5,%6,%7}, {%8,%9}, {%0,%1,%2,%3};"
        : "+f"(d[0]), "+f"(d[1]), "+f"(d[2]), "+f"(d[3])
        : "r"(a[0]), "r"(a[1]), "r"(a[2]), "r"(a[3]), "r"(b0), "r"(b1));
}

// ------------------------------ prep kernels --------------------------------
__device__ __forceinline__ void split_store4(const float* srcp, __nv_bfloat16* dh,
                                             __nv_bfloat16* dl, size_t doff, size_t s4) {
    float4 v = ((const float4*)srcp)[s4];
    float a[4];
    a[0] = v.x; a[1] = v.y; a[2] = v.z; a[3] = v.w;
    __nv_bfloat16 hi[4];
    __nv_bfloat16 lo[4];
    for (int k = 0; k < 4; k++) {
        hi[k] = __float2bfloat16(a[k]);
        lo[k] = __float2bfloat16(a[k] - __bfloat162float(hi[k]));
    }
    *(uint2*)(dh + doff) = *(uint2*)hi;
    *(uint2*)(dl + doff) = *(uint2*)lo;
}

__global__ void k_prep_h(const float* __restrict__ hidden) {
    size_t i = (size_t)blockIdx.x * blockDim.x + threadIdx.x;
    if (i >= (size_t)BSZ * HDIM / 4) return;
    size_t row = i >> 8;
    size_t q = i & 255;
    split_store4(hidden, g_Ah, g_Al, row * KPAD + q * 4, i);
}

__global__ void k_prep_u(const float* __restrict__ Uf, const float* __restrict__ Ui,
                         const float* __restrict__ Uc, const float* __restrict__ Uo) {
    size_t i = (size_t)blockIdx.x * blockDim.x + threadIdx.x;
    if (i >= (size_t)NROW4 * HDIM / 4) return;
    size_t n = i >> 8;
    size_t q = i & 255;
    int g = (int)(n >> 10);
    size_t h = n & 1023;
    const float* Up;
    if (g == 0) Up = Uf;
    else if (g == 1) Up = Ui;
    else if (g == 2) Up = Uc;
    else Up = Uo;
    split_store4(Up, g_Bh, g_Bl, n * KPAD + q * 4, h * 256 + q);
}

__global__ void k_prep_aug(const float* __restrict__ x,
                           const float* __restrict__ Wf, const float* __restrict__ Wi,
                           const float* __restrict__ Wc, const float* __restrict__ Wo,
                           const float* __restrict__ bf, const float* __restrict__ bi,
                           const float* __restrict__ bc, const float* __restrict__ bo) {
    int r = blockIdx.x * blockDim.x + threadIdx.x;
    float v[32];
    for (int m = 0; m < 32; m++) v[m] = 0.0f;
    __nv_bfloat16* dh;
    __nv_bfloat16* dl;
    if (r < BSZ) {
        for (int m = 0; m < INDIM; m++) v[m] = x[r * INDIM + m];
        v[10] = 1.0f;
        dh = g_Ah + (size_t)r * KPAD + 1024;
        dl = g_Al + (size_t)r * KPAD + 1024;
    } else if (r < BSZ + NROW4) {
        int n = r - BSZ;
        int g = n >> 10;
        int h = n & 1023;
        const float* Wp;
        const float* bp;
        if (g == 0) { Wp = Wf; bp = bf; }
        else if (g == 1) { Wp = Wi; bp = bi; }
        else if (g == 2) { Wp = Wc; bp = bc; }
        else { Wp = Wo; bp = bo; }
        for (int m = 0; m < INDIM; m++) v[m] = Wp[h * INDIM + m];
        v[10] = bp[h];
        dh = g_Bh + (size_t)n * KPAD + 1024;
        dl = g_Bl + (size_t)n * KPAD + 1024;
    } else {
        return;
    }
    for (int k = 0; k < 32; k++) {
        __nv_bfloat16 hv = __float2bfloat16(v[k]);
        __nv_bfloat16 lv = __float2bfloat16(v[k] - __bfloat162float(hv));
        dh[k] = hv;
        dl[k] = lv;
    }
}

// --------------------------- gates GEMM (mma.sync) --------------------------
// CTA: 128 rows x 256 cols, 512 threads = 16 warps as 4(m) x 4(n).
// Warp: m32 x n64 -> acc[2 msub][8 nfrag][4]. K chunks of 32, double buffered.
// Smem stage: Ah[128x80] Al[128x80] Bh[256x80] Bl[256x80], 80B row stride.
// Fragments loaded with ldmatrix.x4 (non-trans; layouts verified vs scalar path).

__device__ __forceinline__ void load_chunk(int c, unsigned stg, int b0, int n0, int t) {
    int k0 = c * 32;
    for (int i = 0; i < 6; i++) {
        int u = t + 512 * i;
        if (u < 1024) {
            int half = u >> 9;
            int rr = (u >> 2) & 127;
            int seg = u & 3;
            const __nv_bfloat16* base = (half == 0) ? g_Ah : g_Al;
            const __nv_bfloat16* src = base + (size_t)(b0 + rr) * KPAD + k0 + seg * 8;
            cp16(stg + (unsigned)half * A_HALF + (unsigned)(rr * 80 + seg * 16), src);
        } else {
            int v = u - 1024;
            int half = v >> 10;
            int rr = (v >> 2) & 255;
            int seg = v & 3;
            const __nv_bfloat16* base = (half == 0) ? g_Bh : g_Bl;
            const __nv_bfloat16* src = base + (size_t)(n0 + rr) * KPAD + k0 + seg * 8;
            cp16(stg + 2u * A_HALF + (unsigned)half * B_HALF
                 + (unsigned)(rr * 80 + seg * 16), src);
        }
    }
}

__global__ __launch_bounds__(512) void k_gates_mma() {
    extern __shared__ char smem_raw[];
    unsigned sbase = smem_u32(smem_raw);
    int t = threadIdx.x;
    int b0 = blockIdx.x * 128;
    int n0 = blockIdx.y * 256;
    int w = t >> 5;
    int lane = t & 31;
    int mi = w >> 2;       // 0..3 -> rows mi*32
    int ni = w & 3;        // 0..3 -> cols ni*64
    int gid = lane >> 2;   // 0..7
    int four = lane & 3;   // 0..3
    int g4 = lane >> 3;    // 0..3 ldmatrix address group
    int rl = lane & 7;     // row within group

    // ldmatrix lane-address offsets (within a stage half):
    // A: matrices (r0-7,k0-7),(r8-15,k0-7),(r0-7,k8-15),(r8-15,k8-15)
    unsigned a_lane_off = (unsigned)(((g4 & 1) * 8 + rl) * 80 + (g4 >> 1) * 16);
    // B: matrices (n0-7,k0-7),(n0-7,k8-15),(n8-15,k0-7),(n8-15,k8-15)
    unsigned b_lane_off = (unsigned)(((g4 >> 1) * 8 + rl) * 80 + (g4 & 1) * 16);

    float acc[2][8][4];
    for (int ms = 0; ms < 2; ms++)
        for (int nf = 0; nf < 8; nf++)
            for (int j = 0; j < 4; j++) acc[ms][nf][j] = 0.0f;

    load_chunk(0, sbase, b0, n0, t);
    cp_commit();

    for (int c = 0; c < NCH; c++) {
        unsigned stg = sbase + (unsigned)(c & 1) * STAGE;
        if (c + 1 < NCH) {
            load_chunk(c + 1, sbase + (unsigned)((c + 1) & 1) * STAGE, b0, n0, t);
            cp_commit();
            cp_wait1();
        } else {
            cp_wait0();
        }
        __syncthreads();

        for (int kk = 0; kk < 2; kk++) {
            unsigned kkoff = (unsigned)(kk * 32);
            unsigned ah[2][4];
            unsigned al[2][4];
            for (int ms = 0; ms < 2; ms++) {
                unsigned abase = stg + (unsigned)((mi * 32 + ms * 16) * 80)
                               + kkoff + a_lane_off;
                ldm4(ah[ms], abase);
                ldm4(al[ms], abase + A_HALF);
            }
            unsigned bb = stg + 2u * A_HALF + (unsigned)((ni * 64) * 80)
                        + kkoff + b_lane_off;
            for (int p = 0; p < 4; p++) {
                unsigned bh[4];
                unsigned bl[4];
                unsigned baddr = bb + (unsigned)(p * 16 * 80);
                ldm4(bh, baddr);
                ldm4(bl, baddr + B_HALF);
                for (int ms = 0; ms < 2; ms++) {
                    mma16816(acc[ms][2 * p], ah[ms], bh[0], bh[1]);
                    mma16816(acc[ms][2 * p], ah[ms], bl[0], bl[1]);
                    mma16816(acc[ms][2 * p], al[ms], bh[0], bh[1]);
                    mma16816(acc[ms][2 * p + 1], ah[ms], bh[2], bh[3]);
                    mma16816(acc[ms][2 * p + 1], ah[ms], bl[2], bl[3]);
                    mma16816(acc[ms][2 * p + 1], al[ms], bh[2], bh[3]);
                }
            }
        }
        __syncthreads();
    }

    // store pre-activations
    for (int ms = 0; ms < 2; ms++) {
        for (int nf = 0; nf < 8; nf++) {
            int row = b0 + mi * 32 + ms * 16 + gid;
            int col = n0 + ni * 64 + nf * 8 + four * 2;
            float2 v01;
            v01.x = acc[ms][nf][0];
            v01.y = acc[ms][nf][1];
            *(float2*)(g_P + (size_t)row * NROW4 + col) = v01;
            float2 v23;
            v23.x = acc[ms][nf][2];
            v23.y = acc[ms][nf][3];
            *(float2*)(g_P + (size_t)(row + 8) * NROW4 + col) = v23;
        }
    }
}

// -------------------------- activation epilogue ------------------------------
__device__ __forceinline__ void stb4(__nv_bfloat16* dst, const float* v) {
    __nv_bfloat16 tmp[4];
    for (int j = 0; j < 4; j++) tmp[j] = __float2bfloat16(v[j]);
    *(uint2*)dst = *(uint2*)tmp;
}

__global__ __launch_bounds__(256) void k_act(const float* __restrict__ cin,
                                             float* __restrict__ out) {
    size_t q = (size_t)blockIdx.x * blockDim.x + threadIdx.x;
    if (q >= (size_t)BSZ * 256) return;
    size_t row = q >> 8;
    size_t h4 = (q & 255) * 4;
    const float* prow = g_P + row * NROW4;
    float4 pf = *(const float4*)(prow + h4);
    float4 pi = *(const float4*)(prow + 1024 + h4);
    float4 pc = *(const float4*)(prow + 2048 + h4);
    float4 po = *(const float4*)(prow + 3072 + h4);
    float4 cold = *(const float4*)(cin + row * HDIM + h4);

    float fv[4];
    float iv[4];
    float cv[4];
    float ov[4];
    float cnv[4];
    float hsv[4];
    float af[4] = {pf.x, pf.y, pf.z, pf.w};
    float ai[4] = {pi.x, pi.y, pi.z, pi.w};
    float ac[4] = {pc.x, pc.y, pc.z, pc.w};
    float ao[4] = {po.x, po.y, po.z, po.w};
    float cc[4] = {cold.x, cold.y, cold.z, cold.w};
    for (int j = 0; j < 4; j++) {
        float f = sigmoid_f(af[j]);
        float ii = sigmoid_f(ai[j]);
        float ct = tanhf(ac[j]);
        float o = sigmoid_f(ao[j]);
        float cn = f * cc[j] + ii * ct;
        fv[j] = f;
        iv[j] = ii;
        cv[j] = ct;
        ov[j] = o;
        cnv[j] = cn;
        hsv[j] = o * tanhf(cn);
    }
    size_t ob = row * HDIM + h4;
    *(float4*)(g_R + ob) = make_float4(fv[0], fv[1], fv[2], fv[3]);
    *(float4*)(g_R + BH + ob) = make_float4(iv[0], iv[1], iv[2], iv[3]);
    *(float4*)(g_R + 2 * BH + ob) = make_float4(cv[0], cv[1], cv[2], cv[3]);
    *(float4*)(g_R + 3 * BH + ob) = make_float4(ov[0], ov[1], ov[2], ov[3]);
    *(float4*)(g_R + 4 * BH + ob) = make_float4(cnv[0], cnv[1], cnv[2], cnv[3]);
    *(float4*)(g_R + 5 * BH + ob) = make_float4(hsv[0], hsv[1], hsv[2], hsv[3]);
    *(float4*)(out + BH + ob) = make_float4(cnv[0], cnv[1], cnv[2], cnv[3]);
    stb4(g_Rb + ob, fv);
    stb4(g_Rb + BH + ob, iv);
    stb4(g_Rb + 2 * BH + ob, cv);
    stb4(g_Rb + 3 * BH + ob, ov);
    stb4(g_Rb + 4 * BH + ob, cnv);
    stb4(g_Rb + 5 * BH + ob, hsv);
}

// ------------------------------- GD kernels ---------------------------------
__global__ void k_zero() {
    int i = blockIdx.x * blockDim.x + threadIdx.x;
    if (i < SIXH) {
        g_theta[i] = 0.0f;
        g_grad[i] = 0.0f;
    }
}

__global__ __launch_bounds__(256) void k_gd(const float* __restrict__ mp) {
    __shared__ float sth[SIXH];
    __shared__ float red[8];
    __shared__ float serr;

    int t = threadIdx.x;
    for (int i = t; i < SIXH; i += 256) sth[i] = g_theta[i];
    __syncthreads();

    float gacc[24];
    for (int j = 0; j < 24; j++) gacc[j] = 0.0f;

    float vals[24];
    for (int row = blockIdx.x; row < BSZ; row += gridDim.x) {
        float s = 0.0f;
        for (int j = 0; j < 12; j++) {
            int c0 = 2 * (t + 256 * j);
            int blk = c0 >> 10;
            int off = c0 & 1023;
            __nv_bfloat162 v2 = *(const __nv_bfloat162*)
                (g_Rb + (size_t)blk * BH + (size_t)row * HDIM + off);
            float vx = __bfloat162float(v2.x);
            float vy = __bfloat162float(v2.y);
            vals[2 * j] = vx;
            vals[2 * j + 1] = vy;
            s += vx * sth[c0] + vy * sth[c0 + 1];
        }
        for (int o = 16; o > 0; o >>= 1) s += __shfl_xor_sync(0xffffffffu, s, o);
        if ((t & 31) == 0) red[t >> 5] = s;
        __syncthreads();
        if (t == 0) {
            float e = red[0];
            for (int w = 1; w < 8; w++) e += red[w];
            serr = e - mp[row];
        }
        __syncthreads();
        float err = serr;
        for (int j = 0; j < 24; j++) gacc[j] += err * vals[j];
    }

    for (int j = 0; j < 12; j++) {
        int c0 = 2 * (t + 256 * j);
        atomicAdd(&g_grad[c0], gacc[2 * j]);
        atomicAdd(&g_grad[c0 + 1], gacc[2 * j + 1]);
    }
}

__global__ void k_update() {
    int i = blockIdx.x * blockDim.x + threadIdx.x;
    if (i < SIXH) {
        g_theta[i] -= (2.0f * GD_LR / (float)BSZ) * g_grad[i];
        g_grad[i] = 0.0f;
    }
}

__global__ void k_argmax() {
    __shared__ float ssum[6];
    int t = threadIdx.x;
    if (t < 6) ssum[t] = 0.0f;
    __syncthreads();
    for (int blk = 0; blk < 6; blk++) {
        float p = 0.0f;
        for (int i = t; i < HDIM; i += 256) p += fabsf(g_theta[blk * HDIM + i]);
        for (int o = 16; o > 0; o >>= 1) p += __shfl_xor_sync(0xffffffffu, p, o);
        if ((t & 31) == 0) atomicAdd(&ssum[blk], p);
    }
    __syncthreads();
    if (t == 0) {
        int best = 0;
        float bv = ssum[0];
        for (int b = 1; b < 6; b++) {
            if (ssum[b] > bv) { bv = ssum[b]; best = b; }
        }
        g_argmax = best;
    }
}

__global__ void k_copy(float* __restrict__ out) {
    size_t i = ((size_t)blockIdx.x * 256 + threadIdx.x) * 4;
    int m = g_argmax;
    *(float4*)(out + i) = *(const float4*)(g_R + (size_t)m * BH + i);
}

// ---------------------------------------------------------------------------
extern "C" void kernel_launch(void* const* d_in, const int* in_sizes, int n_in,
                              void* d_out, int out_size)
{
    const float* x      = (const float*)d_in[0];
    const float* hidden = (const float*)d_in[1];
    const float* cin    = (const float*)d_in[2];
    const float* mp     = (const float*)d_in[3];
    const float* Wf     = (const float*)d_in[4];
    const float* bf     = (const float*)d_in[5];
    const float* Uf     = (const float*)d_in[6];
    const float* Wi     = (const float*)d_in[7];
    const float* bi     = (const float*)d_in[8];
    const float* Ui     = (const float*)d_in[9];
    const float* Wc     = (const float*)d_in[10];
    const float* bc     = (const float*)d_in[11];
    const float* Uc     = (const float*)d_in[12];
    const float* Wo     = (const float*)d_in[13];
    const float* bo     = (const float*)d_in[14];
    const float* Uo     = (const float*)d_in[15];
    float* out = (float*)d_out;

    cudaFuncSetAttribute(k_gates_mma, cudaFuncAttributeMaxDynamicSharedMemorySize,
                         SMEM_NEED);

    k_prep_h<<<BSZ * HDIM / 4 / 256, 256>>>(hidden);
    k_prep_u<<<NROW4 * HDIM / 4 / 256, 256>>>(Uf, Ui, Uc, Uo);
    k_prep_aug<<<(BSZ + NROW4) / 256, 256>>>(x, Wf, Wi, Wc, Wo, bf, bi, bc, bo);

    dim3 gg(BSZ / 128, NROW4 / 256);
    k_gates_mma<<<gg, 512, SMEM_NEED>>>();
    k_act<<<BSZ * 256 / 256, 256>>>(cin, out);

    k_zero<<<(SIXH + 255) / 256, 256>>>();
    for (int it = 0; it < GD_ITERS; it++) {
        k_gd<<<592, 256>>>(mp);
        k_update<<<(SIXH + 255) / 256, 256>>>();
    }
    k_argmax<<<1, 256>>>();
    k_copy<<<(int)(BH / 1024ULL), 256>>>(out);
}

// round 16
// speedup vs baseline: 2.7065x; 1.1149x over previous
#include <cuda_runtime.h>
#include <cuda_bf16.h>
#include <math.h>

constexpr int    BSZ      = 16384;
constexpr int    INDIM    = 10;
constexpr int    HDIM     = 1024;
constexpr int    SIXH     = 6144;
constexpr int    GD_ITERS = 7;
constexpr float  GD_LR    = 0.001f;
constexpr size_t BH       = 16777216ULL;   // BSZ * HDIM
constexpr int    KPAD     = 1056;          // 1024 + 32 augmented K cols
constexpr int    NCH      = 33;            // K chunks of 32
constexpr int    NROW4    = 4096;          // 4 * HDIM output cols
constexpr unsigned A_HALF  = 10240u;       // 128 rows * 80
constexpr unsigned B_HALF  = 10240u;       // 128 rows * 80
constexpr unsigned STAGE   = 40960u;       // Ah+Al+Bh+Bl
constexpr int    SMEM_NEED = 81920;        // 2 stages

// ------------------ static device scratch (no allocations) ------------------
__device__ __align__(16) __nv_bfloat16 g_Rb[6 * BH];               // r_t blocks bf16 (GD)
__device__ __align__(16) float g_P[(size_t)BSZ * NROW4];           // pre-activations fp32
__device__ __align__(16) __nv_bfloat16 g_Ah[(size_t)BSZ * KPAD];   // A' hi
__device__ __align__(16) __nv_bfloat16 g_Al[(size_t)BSZ * KPAD];   // A' lo
__device__ __align__(16) __nv_bfloat16 g_Bh[(size_t)NROW4 * KPAD]; // B' hi
__device__ __align__(16) __nv_bfloat16 g_Bl[(size_t)NROW4 * KPAD]; // B' lo
__device__ float g_theta[SIXH];
__device__ float g_grad[SIXH];
__device__ int g_argmax;

__device__ __forceinline__ float sigmoid_f(float v) { return 1.0f / (1.0f + expf(-v)); }

// ------------------------------ PTX helpers ---------------------------------
__device__ __forceinline__ unsigned smem_u32(const void* p) {
    return (unsigned)__cvta_generic_to_shared(p);
}
__device__ __forceinline__ void cp16(unsigned dst, const void* src) {
    asm volatile("cp.async.cg.shared.global [%0], [%1], 16;" :: "r"(dst), "l"(src));
}
__device__ __forceinline__ void cp_commit() {
    asm volatile("cp.async.commit_group;" ::: "memory");
}
__device__ __forceinline__ void cp_wait1() {
    asm volatile("cp.async.wait_group 1;" ::: "memory");
}
__device__ __forceinline__ void cp_wait0() {
    asm volatile("cp.async.wait_group 0;" ::: "memory");
}
__device__ __forceinline__ void ldm4(unsigned* r, unsigned addr) {
    asm volatile(
        "ldmatrix.sync.aligned.m8n8.x4.shared.b16 {%0,%1,%2,%3}, [%4];"
        : "=r"(r[0]), "=r"(r[1]), "=r"(r[2]), "=r"(r[3]) : "r"(addr));
}
__device__ __forceinline__ void mma16816(float* d, const unsigned* a,
                                         unsigned b0, unsigned b1) {
    asm volatile(
        "mma.sync.aligned.m16n8k16.row.col.f32.bf16.bf16.f32 "
        "{%0,%1,%2,%3}, {%4,%5,%6,%7}, {%8,%9}, {%0,%1,%2,%3};"
        : "+f"(d[0]), "+f"(d[1]), "+f"(d[2]), "+f"(d[3])
        : "r"(a[0]), "r"(a[1]), "r"(a[2]), "r"(a[3]), "r"(b0), "r"(b1));
}

// ------------------------------ prep kernels --------------------------------
__device__ __forceinline__ void split_store4(const float* srcp, __nv_bfloat16* dh,
                                             __nv_bfloat16* dl, size_t doff, size_t s4) {
    float4 v = ((const float4*)srcp)[s4];
    float a[4];
    a[0] = v.x; a[1] = v.y; a[2] = v.z; a[3] = v.w;
    __nv_bfloat16 hi[4];
    __nv_bfloat16 lo[4];
    for (int k = 0; k < 4; k++) {
        hi[k] = __float2bfloat16(a[k]);
        lo[k] = __float2bfloat16(a[k] - __bfloat162float(hi[k]));
    }
    *(uint2*)(dh + doff) = *(uint2*)hi;
    *(uint2*)(dl + doff) = *(uint2*)lo;
}

__global__ void k_prep_h(const float* __restrict__ hidden) {
    size_t i = (size_t)blockIdx.x * blockDim.x + threadIdx.x;
    if (i >= (size_t)BSZ * HDIM / 4) return;
    size_t row = i >> 8;
    size_t q = i & 255;
    split_store4(hidden, g_Ah, g_Al, row * KPAD + q * 4, i);
}

__global__ void k_prep_u(const float* __restrict__ Uf, const float* __restrict__ Ui,
                         const float* __restrict__ Uc, const float* __restrict__ Uo) {
    size_t i = (size_t)blockIdx.x * blockDim.x + threadIdx.x;
    if (i >= (size_t)NROW4 * HDIM / 4) return;
    size_t n = i >> 8;
    size_t q = i & 255;
    int g = (int)(n >> 10);
    size_t h = n & 1023;
    const float* Up;
    if (g == 0) Up = Uf;
    else if (g == 1) Up = Ui;
    else if (g == 2) Up = Uc;
    else Up = Uo;
    split_store4(Up, g_Bh, g_Bl, n * KPAD + q * 4, h * 256 + q);
}

__global__ void k_prep_aug(const float* __restrict__ x,
                           const float* __restrict__ Wf, const float* __restrict__ Wi,
                           const float* __restrict__ Wc, const float* __restrict__ Wo,
                           const float* __restrict__ bf, const float* __restrict__ bi,
                           const float* __restrict__ bc, const float* __restrict__ bo) {
    int r = blockIdx.x * blockDim.x + threadIdx.x;
    float v[32];
    for (int m = 0; m < 32; m++) v[m] = 0.0f;
    __nv_bfloat16* dh;
    __nv_bfloat16* dl;
    if (r < BSZ) {
        for (int m = 0; m < INDIM; m++) v[m] = x[r * INDIM + m];
        v[10] = 1.0f;
        dh = g_Ah + (size_t)r * KPAD + 1024;
        dl = g_Al + (size_t)r * KPAD + 1024;
    } else if (r < BSZ + NROW4) {
        int n = r - BSZ;
        int g = n >> 10;
        int h = n & 1023;
        const float* Wp;
        const float* bp;
        if (g == 0) { Wp = Wf; bp = bf; }
        else if (g == 1) { Wp = Wi; bp = bi; }
        else if (g == 2) { Wp = Wc; bp = bc; }
        else { Wp = Wo; bp = bo; }
        for (int m = 0; m < INDIM; m++) v[m] = Wp[h * INDIM + m];
        v[10] = bp[h];
        dh = g_Bh + (size_t)n * KPAD + 1024;
        dl = g_Bl + (size_t)n * KPAD + 1024;
    } else {
        return;
    }
    for (int k = 0; k < 32; k++) {
        __nv_bfloat16 hv = __float2bfloat16(v[k]);
        __nv_bfloat16 lv = __float2bfloat16(v[k] - __bfloat162float(hv));
        dh[k] = hv;
        dl[k] = lv;
    }
}

// --------------------------- gates GEMM (mma.sync) --------------------------
// CTA: 128 rows x 128 cols, 256 threads = 8 warps as 4(m) x 2(n) -> 2 CTAs/SM.
// Warp: m32 x n64 -> acc[2 msub][8 nfrag][4]. K chunks of 32, double buffered.
// Smem stage: Ah[128x80] Al[128x80] Bh[128x80] Bl[128x80], 80B row stride.
// Fragments via ldmatrix.x4 (layouts verified against scalar path in R13).

__device__ __forceinline__ void load_chunk(int c, unsigned stg, int b0, int n0, int t) {
    int k0 = c * 32;
    for (int i = 0; i < 8; i++) {
        int u = t + 256 * i;
        if (u < 1024) {
            int half = u >> 9;
            int rr = (u >> 2) & 127;
            int seg = u & 3;
            const __nv_bfloat16* base = (half == 0) ? g_Ah : g_Al;
            const __nv_bfloat16* src = base + (size_t)(b0 + rr) * KPAD + k0 + seg * 8;
            cp16(stg + (unsigned)half * A_HALF + (unsigned)(rr * 80 + seg * 16), src);
        } else {
            int v = u - 1024;
            int half = v >> 9;
            int rr = (v >> 2) & 127;
            int seg = v & 3;
            const __nv_bfloat16* base = (half == 0) ? g_Bh : g_Bl;
            const __nv_bfloat16* src = base + (size_t)(n0 + rr) * KPAD + k0 + seg * 8;
            cp16(stg + 2u * A_HALF + (unsigned)half * B_HALF
                 + (unsigned)(rr * 80 + seg * 16), src);
        }
    }
}

__global__ __launch_bounds__(256, 2) void k_gates_mma() {
    extern __shared__ char smem_raw[];
    unsigned sbase = smem_u32(smem_raw);
    int t = threadIdx.x;
    int b0 = blockIdx.x * 128;
    int n0 = blockIdx.y * 128;
    int w = t >> 5;
    int lane = t & 31;
    int mi = w >> 1;       // 0..3 -> rows mi*32
    int ni = w & 1;        // 0..1 -> cols ni*64
    int gid = lane >> 2;   // 0..7
    int four = lane & 3;   // 0..3
    int g4 = lane >> 3;    // 0..3 ldmatrix address group
    int rl = lane & 7;     // row within group

    // ldmatrix lane-address offsets (within a stage half):
    unsigned a_lane_off = (unsigned)(((g4 & 1) * 8 + rl) * 80 + (g4 >> 1) * 16);
    unsigned b_lane_off = (unsigned)(((g4 >> 1) * 8 + rl) * 80 + (g4 & 1) * 16);

    float acc[2][8][4];
    for (int ms = 0; ms < 2; ms++)
        for (int nf = 0; nf < 8; nf++)
            for (int j = 0; j < 4; j++) acc[ms][nf][j] = 0.0f;

    load_chunk(0, sbase, b0, n0, t);
    cp_commit();

    for (int c = 0; c < NCH; c++) {
        unsigned stg = sbase + (unsigned)(c & 1) * STAGE;
        if (c + 1 < NCH) {
            load_chunk(c + 1, sbase + (unsigned)((c + 1) & 1) * STAGE, b0, n0, t);
            cp_commit();
            cp_wait1();
        } else {
            cp_wait0();
        }
        __syncthreads();

        for (int kk = 0; kk < 2; kk++) {
            unsigned kkoff = (unsigned)(kk * 32);
            unsigned ah[2][4];
            unsigned al[2][4];
            for (int ms = 0; ms < 2; ms++) {
                unsigned abase = stg + (unsigned)((mi * 32 + ms * 16) * 80)
                               + kkoff + a_lane_off;
                ldm4(ah[ms], abase);
                ldm4(al[ms], abase + A_HALF);
            }
            unsigned bb = stg + 2u * A_HALF + (unsigned)((ni * 64) * 80)
                        + kkoff + b_lane_off;
            for (int p = 0; p < 4; p++) {
                unsigned bh[4];
                unsigned bl[4];
                unsigned baddr = bb + (unsigned)(p * 16 * 80);
                ldm4(bh, baddr);
                ldm4(bl, baddr + B_HALF);
                for (int ms = 0; ms < 2; ms++) {
                    mma16816(acc[ms][2 * p], ah[ms], bh[0], bh[1]);
                    mma16816(acc[ms][2 * p], ah[ms], bl[0], bl[1]);
                    mma16816(acc[ms][2 * p], al[ms], bh[0], bh[1]);
                    mma16816(acc[ms][2 * p + 1], ah[ms], bh[2], bh[3]);
                    mma16816(acc[ms][2 * p + 1], ah[ms], bl[2], bl[3]);
                    mma16816(acc[ms][2 * p + 1], al[ms], bh[2], bh[3]);
                }
            }
        }
        __syncthreads();
    }

    // store pre-activations
    for (int ms = 0; ms < 2; ms++) {
        for (int nf = 0; nf < 8; nf++) {
            int row = b0 + mi * 32 + ms * 16 + gid;
            int col = n0 + ni * 64 + nf * 8 + four * 2;
            float2 v01;
            v01.x = acc[ms][nf][0];
            v01.y = acc[ms][nf][1];
            *(float2*)(g_P + (size_t)row * NROW4 + col) = v01;
            float2 v23;
            v23.x = acc[ms][nf][2];
            v23.y = acc[ms][nf][3];
            *(float2*)(g_P + (size_t)(row + 8) * NROW4 + col) = v23;
        }
    }
}

// -------------------------- activation epilogue ------------------------------
__device__ __forceinline__ void stb4(__nv_bfloat16* dst, const float* v) {
    __nv_bfloat16 tmp[4];
    for (int j = 0; j < 4; j++) tmp[j] = __float2bfloat16(v[j]);
    *(uint2*)dst = *(uint2*)tmp;
}

__global__ __launch_bounds__(256) void k_act(const float* __restrict__ cin,
                                             float* __restrict__ out) {
    size_t q = (size_t)blockIdx.x * blockDim.x + threadIdx.x;
    if (q >= (size_t)BSZ * 256) return;
    size_t row = q >> 8;
    size_t h4 = (q & 255) * 4;
    const float* prow = g_P + row * NROW4;
    float4 pf = *(const float4*)(prow + h4);
    float4 pi = *(const float4*)(prow + 1024 + h4);
    float4 pc = *(const float4*)(prow + 2048 + h4);
    float4 po = *(const float4*)(prow + 3072 + h4);
    float4 cold = *(const float4*)(cin + row * HDIM + h4);

    float fv[4];
    float iv[4];
    float cv[4];
    float ov[4];
    float cnv[4];
    float hsv[4];
    float af[4] = {pf.x, pf.y, pf.z, pf.w};
    float ai[4] = {pi.x, pi.y, pi.z, pi.w};
    float ac[4] = {pc.x, pc.y, pc.z, pc.w};
    float ao[4] = {po.x, po.y, po.z, po.w};
    float cc[4] = {cold.x, cold.y, cold.z, cold.w};
    for (int j = 0; j < 4; j++) {
        float f = sigmoid_f(af[j]);
        float ii = sigmoid_f(ai[j]);
        float ct = tanhf(ac[j]);
        float o = sigmoid_f(ao[j]);
        float cn = f * cc[j] + ii * ct;
        fv[j] = f;
        iv[j] = ii;
        cv[j] = ct;
        ov[j] = o;
        cnv[j] = cn;
        hsv[j] = o * tanhf(cn);
    }
    size_t ob = row * HDIM + h4;
    *(float4*)(out + BH + ob) = make_float4(cnv[0], cnv[1], cnv[2], cnv[3]);
    stb4(g_Rb + ob, fv);
    stb4(g_Rb + BH + ob, iv);
    stb4(g_Rb + 2 * BH + ob, cv);
    stb4(g_Rb + 3 * BH + ob, ov);
    stb4(g_Rb + 4 * BH + ob, cnv);
    stb4(g_Rb + 5 * BH + ob, hsv);
}

// ------------------------------- GD kernels ---------------------------------
__global__ void k_zero() {
    int i = blockIdx.x * blockDim.x + threadIdx.x;
    if (i < SIXH) {
        g_theta[i] = 0.0f;
        g_grad[i] = 0.0f;
    }
}

__global__ __launch_bounds__(256) void k_gd(const float* __restrict__ mp) {
    __shared__ float sth[SIXH];
    __shared__ float red[8];
    __shared__ float serr;

    int t = threadIdx.x;
    for (int i = t; i < SIXH; i += 256) sth[i] = g_theta[i];
    __syncthreads();

    float gacc[24];
    for (int j = 0; j < 24; j++) gacc[j] = 0.0f;

    float vals[24];
    for (int row = blockIdx.x; row < BSZ; row += gridDim.x) {
        float s = 0.0f;
        for (int j = 0; j < 12; j++) {
            int c0 = 2 * (t + 256 * j);
            int blk = c0 >> 10;
            int off = c0 & 1023;
            __nv_bfloat162 v2 = *(const __nv_bfloat162*)
                (g_Rb + (size_t)blk * BH + (size_t)row * HDIM + off);
            float vx = __bfloat162float(v2.x);
            float vy = __bfloat162float(v2.y);
            vals[2 * j] = vx;
            vals[2 * j + 1] = vy;
            s += vx * sth[c0] + vy * sth[c0 + 1];
        }
        for (int o = 16; o > 0; o >>= 1) s += __shfl_xor_sync(0xffffffffu, s, o);
        if ((t & 31) == 0) red[t >> 5] = s;
        __syncthreads();
        if (t == 0) {
            float e = red[0];
            for (int w = 1; w < 8; w++) e += red[w];
            serr = e - mp[row];
        }
        __syncthreads();
        float err = serr;
        for (int j = 0; j < 24; j++) gacc[j] += err * vals[j];
    }

    for (int j = 0; j < 12; j++) {
        int c0 = 2 * (t + 256 * j);
        atomicAdd(&g_grad[c0], gacc[2 * j]);
        atomicAdd(&g_grad[c0 + 1], gacc[2 * j + 1]);
    }
}

__global__ void k_update() {
    int i = blockIdx.x * blockDim.x + threadIdx.x;
    if (i < SIXH) {
        g_theta[i] -= (2.0f * GD_LR / (float)BSZ) * g_grad[i];
        g_grad[i] = 0.0f;
    }
}

__global__ void k_argmax() {
    __shared__ float ssum[6];
    int t = threadIdx.x;
    if (t < 6) ssum[t] = 0.0f;
    __syncthreads();
    for (int blk = 0; blk < 6; blk++) {
        float p = 0.0f;
        for (int i = t; i < HDIM; i += 256) p += fabsf(g_theta[blk * HDIM + i]);
        for (int o = 16; o > 0; o >>= 1) p += __shfl_xor_sync(0xffffffffu, p, o);
        if ((t & 31) == 0) atomicAdd(&ssum[blk], p);
    }
    __syncthreads();
    if (t == 0) {
        int best = 0;
        float bv = ssum[0];
        for (int b = 1; b < 6; b++) {
            if (ssum[b] > bv) { bv = ssum[b]; best = b; }
        }
        g_argmax = best;
    }
}

// h_new recomputed from fp32 g_P (same formulas as k_act -> bit-identical):
// m in {0,1,3}: sigmoid(P block m); m==2: tanh(P block 2);
// m==4: copy c_new from out[BH..]; m==5: sigmoid(P blk3) * tanh(c_new).
__global__ __launch_bounds__(256) void k_finalize(float* __restrict__ out) {
    size_t i = ((size_t)blockIdx.x * 256 + threadIdx.x) * 4;
    if (i >= BH) return;
    int m = g_argmax;
    size_t row = i >> 10;
    size_t h4 = i & 1023;
    float4 r;
    if (m == 4) {
        r = *(const float4*)(out + BH + i);
    } else if (m == 5) {
        float4 po = *(const float4*)(g_P + row * NROW4 + 3072 + h4);
        float4 cn = *(const float4*)(out + BH + i);
        r.x = sigmoid_f(po.x) * tanhf(cn.x);
        r.y = sigmoid_f(po.y) * tanhf(cn.y);
        r.z = sigmoid_f(po.z) * tanhf(cn.z);
        r.w = sigmoid_f(po.w) * tanhf(cn.w);
    } else {
        float4 p = *(const float4*)(g_P + row * NROW4 + (size_t)m * 1024 + h4);
        if (m == 2) {
            r.x = tanhf(p.x);
            r.y = tanhf(p.y);
            r.z = tanhf(p.z);
            r.w = tanhf(p.w);
        } else {
            r.x = sigmoid_f(p.x);
            r.y = sigmoid_f(p.y);
            r.z = sigmoid_f(p.z);
            r.w = sigmoid_f(p.w);
        }
    }
    *(float4*)(out + i) = r;
}

// ---------------------------------------------------------------------------
extern "C" void kernel_launch(void* const* d_in, const int* in_sizes, int n_in,
                              void* d_out, int out_size)
{
    const float* x      = (const float*)d_in[0];
    const float* hidden = (const float*)d_in[1];
    const float* cin    = (const float*)d_in[2];
    const float* mp     = (const float*)d_in[3];
    const float* Wf     = (const float*)d_in[4];
    const float* bf     = (const float*)d_in[5];
    const float* Uf     = (const float*)d_in[6];
    const float* Wi     = (const float*)d_in[7];
    const float* bi     = (const float*)d_in[8];
    const float* Ui     = (const float*)d_in[9];
    const float* Wc     = (const float*)d_in[10];
    const float* bc     = (const float*)d_in[11];
    const float* Uc     = (const float*)d_in[12];
    const float* Wo     = (const float*)d_in[13];
    const float* bo     = (const float*)d_in[14];
    const float* Uo     = (const float*)d_in[15];
    float* out = (float*)d_out;

    cudaFuncSetAttribute(k_gates_mma, cudaFuncAttributeMaxDynamicSharedMemorySize,
                         SMEM_NEED);

    k_prep_h<<<BSZ * HDIM / 4 / 256, 256>>>(hidden);
    k_prep_u<<<NROW4 * HDIM / 4 / 256, 256>>>(Uf, Ui, Uc, Uo);
    k_prep_aug<<<(BSZ + NROW4) / 256, 256>>>(x, Wf, Wi, Wc, Wo, bf, bi, bc, bo);

    dim3 gg(BSZ / 128, NROW4 / 128);
    k_gates_mma<<<gg, 256, SMEM_NEED>>>();
    k_act<<<BSZ * 256 / 256, 256>>>(cin, out);

    k_zero<<<(SIXH + 255) / 256, 256>>>();
    for (int it = 0; it < GD_ITERS; it++) {
        k_gd<<<592, 256>>>(mp);
        k_update<<<(SIXH + 255) / 256, 256>>>();
    }
    k_argmax<<<1, 256>>>();
    k_finalize<<<(int)(BH / 1024ULL), 256>>>(out);
}

// round 17
// speedup vs baseline: 2.7710x; 1.0238x over previous
#include <cuda_runtime.h>
#include <cuda_bf16.h>
#include <math.h>

constexpr int    BSZ      = 16384;
constexpr int    INDIM    = 10;
constexpr int    HDIM     = 1024;
constexpr int    SIXH     = 6144;
constexpr int    GD_ITERS = 7;
constexpr float  GD_LR    = 0.001f;
constexpr size_t BH       = 16777216ULL;   // BSZ * HDIM
constexpr int    KPAD     = 1056;          // 1024 + 32 augmented K cols
constexpr int    NCH      = 33;            // K chunks of 32
constexpr int    NROW4    = 4096;          // 4 * HDIM output cols
constexpr unsigned A_HALF  = 10240u;       // 128 rows * 80
constexpr unsigned B_HALF  = 10240u;       // 128 rows * 80
constexpr unsigned STAGE   = 40960u;       // Ah+Al+Bh+Bl
constexpr int    SMEM_NEED = 81920;        // 2 stages

// ------------------ static device scratch (no allocations) ------------------
__device__ __align__(16) __nv_bfloat16 g_Rb[6 * BH];               // r_t blocks bf16 (GD)
__device__ __align__(16) float g_P[(size_t)BSZ * NROW4];           // pre-activations fp32
__device__ __align__(16) __nv_bfloat16 g_Ah[(size_t)BSZ * KPAD];   // A' hi
__device__ __align__(16) __nv_bfloat16 g_Al[(size_t)BSZ * KPAD];   // A' lo
__device__ __align__(16) __nv_bfloat16 g_Bh[(size_t)NROW4 * KPAD]; // B' hi
__device__ __align__(16) __nv_bfloat16 g_Bl[(size_t)NROW4 * KPAD]; // B' lo
__device__ float g_theta[SIXH];
__device__ float g_grad[SIXH];
__device__ int g_argmax;

__device__ __forceinline__ float sigmoid_f(float v) { return 1.0f / (1.0f + expf(-v)); }

// ------------------------------ PTX helpers ---------------------------------
__device__ __forceinline__ unsigned smem_u32(const void* p) {
    return (unsigned)__cvta_generic_to_shared(p);
}
__device__ __forceinline__ void cp16(unsigned dst, const void* src) {
    asm volatile("cp.async.cg.shared.global [%0], [%1], 16;" :: "r"(dst), "l"(src));
}
__device__ __forceinline__ void cp_commit() {
    asm volatile("cp.async.commit_group;" ::: "memory");
}
__device__ __forceinline__ void cp_wait1() {
    asm volatile("cp.async.wait_group 1;" ::: "memory");
}
__device__ __forceinline__ void cp_wait0() {
    asm volatile("cp.async.wait_group 0;" ::: "memory");
}
__device__ __forceinline__ void ldm4(unsigned* r, unsigned addr) {
    asm volatile(
        "ldmatrix.sync.aligned.m8n8.x4.shared.b16 {%0,%1,%2,%3}, [%4];"
        : "=r"(r[0]), "=r"(r[1]), "=r"(r[2]), "=r"(r[3]) : "r"(addr));
}
__device__ __forceinline__ void mma16816(float* d, const unsigned* a,
                                         unsigned b0, unsigned b1) {
    asm volatile(
        "mma.sync.aligned.m16n8k16.row.col.f32.bf16.bf16.f32 "
        "{%0,%1,%2,%3}, {%4,%5,%6,%7}, {%8,%9}, {%0,%1,%2,%3};"
        : "+f"(d[0]), "+f"(d[1]), "+f"(d[2]), "+f"(d[3])
        : "r"(a[0]), "r"(a[1]), "r"(a[2]), "r"(a[3]), "r"(b0), "r"(b1));
}

// ------------------------------ prep kernels --------------------------------
__device__ __forceinline__ void split_store4(const float* srcp, __nv_bfloat16* dh,
                                             __nv_bfloat16* dl, size_t doff, size_t s4) {
    float4 v = ((const float4*)srcp)[s4];
    float a[4];
    a[0] = v.x; a[1] = v.y; a[2] = v.z; a[3] = v.w;
    __nv_bfloat16 hi[4];
    __nv_bfloat16 lo[4];
    for (int k = 0; k < 4; k++) {
        hi[k] = __float2bfloat16(a[k]);
        lo[k] = __float2bfloat16(a[k] - __bfloat162float(hi[k]));
    }
    *(uint2*)(dh + doff) = *(uint2*)hi;
    *(uint2*)(dl + doff) = *(uint2*)lo;
}

__global__ void k_prep_h(const float* __restrict__ hidden) {
    size_t i = (size_t)blockIdx.x * blockDim.x + threadIdx.x;
    if (i >= (size_t)BSZ * HDIM / 4) return;
    size_t row = i >> 8;
    size_t q = i & 255;
    split_store4(hidden, g_Ah, g_Al, row * KPAD + q * 4, i);
}

__global__ void k_prep_u(const float* __restrict__ Uf, const float* __restrict__ Ui,
                         const float* __restrict__ Uc, const float* __restrict__ Uo) {
    size_t i = (size_t)blockIdx.x * blockDim.x + threadIdx.x;
    if (i >= (size_t)NROW4 * HDIM / 4) return;
    size_t n = i >> 8;
    size_t q = i & 255;
    int g = (int)(n >> 10);
    size_t h = n & 1023;
    const float* Up;
    if (g == 0) Up = Uf;
    else if (g == 1) Up = Ui;
    else if (g == 2) Up = Uc;
    else Up = Uo;
    split_store4(Up, g_Bh, g_Bl, n * KPAD + q * 4, h * 256 + q);
}

__global__ void k_prep_aug(const float* __restrict__ x,
                           const float* __restrict__ Wf, const float* __restrict__ Wi,
                           const float* __restrict__ Wc, const float* __restrict__ Wo,
                           const float* __restrict__ bf, const float* __restrict__ bi,
                           const float* __restrict__ bc, const float* __restrict__ bo) {
    int r = blockIdx.x * blockDim.x + threadIdx.x;
    float v[32];
    for (int m = 0; m < 32; m++) v[m] = 0.0f;
    __nv_bfloat16* dh;
    __nv_bfloat16* dl;
    if (r < BSZ) {
        for (int m = 0; m < INDIM; m++) v[m] = x[r * INDIM + m];
        v[10] = 1.0f;
        dh = g_Ah + (size_t)r * KPAD + 1024;
        dl = g_Al + (size_t)r * KPAD + 1024;
    } else if (r < BSZ + NROW4) {
        int n = r - BSZ;
        int g = n >> 10;
        int h = n & 1023;
        const float* Wp;
        const float* bp;
        if (g == 0) { Wp = Wf; bp = bf; }
        else if (g == 1) { Wp = Wi; bp = bi; }
        else if (g == 2) { Wp = Wc; bp = bc; }
        else { Wp = Wo; bp = bo; }
        for (int m = 0; m < INDIM; m++) v[m] = Wp[h * INDIM + m];
        v[10] = bp[h];
        dh = g_Bh + (size_t)n * KPAD + 1024;
        dl = g_Bl + (size_t)n * KPAD + 1024;
    } else {
        return;
    }
    for (int k = 0; k < 32; k++) {
        __nv_bfloat16 hv = __float2bfloat16(v[k]);
        __nv_bfloat16 lv = __float2bfloat16(v[k] - __bfloat162float(hv));
        dh[k] = hv;
        dl[k] = lv;
    }
}

// --------------------------- gates GEMM (mma.sync) --------------------------
// CTA: 128 rows x 128 cols, 128 threads = 4 warps as 2(m) x 2(n), 2 CTAs/SM.
// Warp tile: m64 x n64 -> acc[4 msub][8 nfrag][4] = 128 regs; 96 MMAs per
// 8KB of fragment loads (3:1 tensor:smem). K chunks of 32, double buffered.
// MMA issue order interleaves accumulators so same-acc MMAs are 8 apart.

__device__ __forceinline__ void load_chunk(int c, unsigned stg, int b0, int n0, int t) {
    int k0 = c * 32;
    for (int i = 0; i < 16; i++) {
        int u = t + 128 * i;
        if (u < 1024) {
            int half = u >> 9;
            int rr = (u >> 2) & 127;
            int seg = u & 3;
            const __nv_bfloat16* base = (half == 0) ? g_Ah : g_Al;
            const __nv_bfloat16* src = base + (size_t)(b0 + rr) * KPAD + k0 + seg * 8;
            cp16(stg + (unsigned)half * A_HALF + (unsigned)(rr * 80 + seg * 16), src);
        } else {
            int v = u - 1024;
            int half = v >> 9;
            int rr = (v >> 2) & 127;
            int seg = v & 3;
            const __nv_bfloat16* base = (half == 0) ? g_Bh : g_Bl;
            const __nv_bfloat16* src = base + (size_t)(n0 + rr) * KPAD + k0 + seg * 8;
            cp16(stg + 2u * A_HALF + (unsigned)half * B_HALF
                 + (unsigned)(rr * 80 + seg * 16), src);
        }
    }
}

__global__ __launch_bounds__(128, 2) void k_gates_mma() {
    extern __shared__ char smem_raw[];
    unsigned sbase = smem_u32(smem_raw);
    int t = threadIdx.x;
    int b0 = blockIdx.x * 128;
    int n0 = blockIdx.y * 128;
    int w = t >> 5;
    int lane = t & 31;
    int mi = w >> 1;       // 0..1 -> rows mi*64
    int ni = w & 1;        // 0..1 -> cols ni*64
    int gid = lane >> 2;   // 0..7
    int four = lane & 3;   // 0..3
    int g4 = lane >> 3;    // 0..3 ldmatrix address group
    int rl = lane & 7;     // row within group

    // ldmatrix lane-address offsets (within a stage half):
    unsigned a_lane_off = (unsigned)(((g4 & 1) * 8 + rl) * 80 + (g4 >> 1) * 16);
    unsigned b_lane_off = (unsigned)(((g4 >> 1) * 8 + rl) * 80 + (g4 & 1) * 16);

    float acc[4][8][4];
    for (int ms = 0; ms < 4; ms++)
        for (int nf = 0; nf < 8; nf++)
            for (int j = 0; j < 4; j++) acc[ms][nf][j] = 0.0f;

    load_chunk(0, sbase, b0, n0, t);
    cp_commit();

    for (int c = 0; c < NCH; c++) {
        unsigned stg = sbase + (unsigned)(c & 1) * STAGE;
        if (c + 1 < NCH) {
            load_chunk(c + 1, sbase + (unsigned)((c + 1) & 1) * STAGE, b0, n0, t);
            cp_commit();
            cp_wait1();
        } else {
            cp_wait0();
        }
        __syncthreads();

        for (int kk = 0; kk < 2; kk++) {
            unsigned kkoff = (unsigned)(kk * 32);
            unsigned ah[4][4];
            unsigned al[4][4];
            for (int ms = 0; ms < 4; ms++) {
                unsigned abase = stg + (unsigned)((mi * 64 + ms * 16) * 80)
                               + kkoff + a_lane_off;
                ldm4(ah[ms], abase);
                ldm4(al[ms], abase + A_HALF);
            }
            unsigned bb = stg + 2u * A_HALF + (unsigned)((ni * 64) * 80)
                        + kkoff + b_lane_off;
            for (int p = 0; p < 4; p++) {
                unsigned bh[4];
                unsigned bl[4];
                unsigned baddr = bb + (unsigned)(p * 16 * 80);
                ldm4(bh, baddr);
                ldm4(bl, baddr + B_HALF);
                // term 1: ah x bh  (8 independent accumulators back-to-back)
                for (int ms = 0; ms < 4; ms++) {
                    mma16816(acc[ms][2 * p], ah[ms], bh[0], bh[1]);
                    mma16816(acc[ms][2 * p + 1], ah[ms], bh[2], bh[3]);
                }
                // term 2: ah x bl
                for (int ms = 0; ms < 4; ms++) {
                    mma16816(acc[ms][2 * p], ah[ms], bl[0], bl[1]);
                    mma16816(acc[ms][2 * p + 1], ah[ms], bl[2], bl[3]);
                }
                // term 3: al x bh
                for (int ms = 0; ms < 4; ms++) {
                    mma16816(acc[ms][2 * p], al[ms], bh[0], bh[1]);
                    mma16816(acc[ms][2 * p + 1], al[ms], bh[2], bh[3]);
                }
            }
        }
        __syncthreads();
    }

    // store pre-activations
    for (int ms = 0; ms < 4; ms++) {
        for (int nf = 0; nf < 8; nf++) {
            int row = b0 + mi * 64 + ms * 16 + gid;
            int col = n0 + ni * 64 + nf * 8 + four * 2;
            float2 v01;
            v01.x = acc[ms][nf][0];
            v01.y = acc[ms][nf][1];
            *(float2*)(g_P + (size_t)row * NROW4 + col) = v01;
            float2 v23;
            v23.x = acc[ms][nf][2];
            v23.y = acc[ms][nf][3];
            *(float2*)(g_P + (size_t)(row + 8) * NROW4 + col) = v23;
        }
    }
}

// -------------------------- activation epilogue ------------------------------
__device__ __forceinline__ void stb4(__nv_bfloat16* dst, const float* v) {
    __nv_bfloat16 tmp[4];
    for (int j = 0; j < 4; j++) tmp[j] = __float2bfloat16(v[j]);
    *(uint2*)dst = *(uint2*)tmp;
}

__global__ __launch_bounds__(256) void k_act(const float* __restrict__ cin,
                                             float* __restrict__ out) {
    size_t q = (size_t)blockIdx.x * blockDim.x + threadIdx.x;
    if (q >= (size_t)BSZ * 256) return;
    size_t row = q >> 8;
    size_t h4 = (q & 255) * 4;
    const float* prow = g_P + row * NROW4;
    float4 pf = *(const float4*)(prow + h4);
    float4 pi = *(const float4*)(prow + 1024 + h4);
    float4 pc = *(const float4*)(prow + 2048 + h4);
    float4 po = *(const float4*)(prow + 3072 + h4);
    float4 cold = *(const float4*)(cin + row * HDIM + h4);

    float fv[4];
    float iv[4];
    float cv[4];
    float ov[4];
    float cnv[4];
    float hsv[4];
    float af[4] = {pf.x, pf.y, pf.z, pf.w};
    float ai[4] = {pi.x, pi.y, pi.z, pi.w};
    float ac[4] = {pc.x, pc.y, pc.z, pc.w};
    float ao[4] = {po.x, po.y, po.z, po.w};
    float cc[4] = {cold.x, cold.y, cold.z, cold.w};
    for (int j = 0; j < 4; j++) {
        float f = sigmoid_f(af[j]);
        float ii = sigmoid_f(ai[j]);
        float ct = tanhf(ac[j]);
        float o = sigmoid_f(ao[j]);
        float cn = f * cc[j] + ii * ct;
        fv[j] = f;
        iv[j] = ii;
        cv[j] = ct;
        ov[j] = o;
        cnv[j] = cn;
        hsv[j] = o * tanhf(cn);
    }
    size_t ob = row * HDIM + h4;
    *(float4*)(out + BH + ob) = make_float4(cnv[0], cnv[1], cnv[2], cnv[3]);
    stb4(g_Rb + ob, fv);
    stb4(g_Rb + BH + ob, iv);
    stb4(g_Rb + 2 * BH + ob, cv);
    stb4(g_Rb + 3 * BH + ob, ov);
    stb4(g_Rb + 4 * BH + ob, cnv);
    stb4(g_Rb + 5 * BH + ob, hsv);
}

// ------------------------------- GD kernels ---------------------------------
__global__ void k_zero() {
    int i = blockIdx.x * blockDim.x + threadIdx.x;
    if (i < SIXH) {
        g_theta[i] = 0.0f;
        g_grad[i] = 0.0f;
    }
}

__global__ __launch_bounds__(256) void k_gd(const float* __restrict__ mp) {
    __shared__ float sth[SIXH];
    __shared__ float red[8];
    __shared__ float serr;

    int t = threadIdx.x;
    for (int i = t; i < SIXH; i += 256) sth[i] = g_theta[i];
    __syncthreads();

    float gacc[24];
    for (int j = 0; j < 24; j++) gacc[j] = 0.0f;

    float vals[24];
    for (int row = blockIdx.x; row < BSZ; row += gridDim.x) {
        float s = 0.0f;
        for (int j = 0; j < 12; j++) {
            int c0 = 2 * (t + 256 * j);
            int blk = c0 >> 10;
            int off = c0 & 1023;
            __nv_bfloat162 v2 = *(const __nv_bfloat162*)
                (g_Rb + (size_t)blk * BH + (size_t)row * HDIM + off);
            float vx = __bfloat162float(v2.x);
            float vy = __bfloat162float(v2.y);
            vals[2 * j] = vx;
            vals[2 * j + 1] = vy;
            s += vx * sth[c0] + vy * sth[c0 + 1];
        }
        for (int o = 16; o > 0; o >>= 1) s += __shfl_xor_sync(0xffffffffu, s, o);
        if ((t & 31) == 0) red[t >> 5] = s;
        __syncthreads();
        if (t == 0) {
            float e = red[0];
            for (int w = 1; w < 8; w++) e += red[w];
            serr = e - mp[row];
        }
        __syncthreads();
        float err = serr;
        for (int j = 0; j < 24; j++) gacc[j] += err * vals[j];
    }

    for (int j = 0; j < 12; j++) {
        int c0 = 2 * (t + 256 * j);
        atomicAdd(&g_grad[c0], gacc[2 * j]);
        atomicAdd(&g_grad[c0 + 1], gacc[2 * j + 1]);
    }
}

__global__ void k_update() {
    int i = blockIdx.x * blockDim.x + threadIdx.x;
    if (i < SIXH) {
        g_theta[i] -= (2.0f * GD_LR / (float)BSZ) * g_grad[i];
        g_grad[i] = 0.0f;
    }
}

__global__ void k_argmax() {
    __shared__ float ssum[6];
    int t = threadIdx.x;
    if (t < 6) ssum[t] = 0.0f;
    __syncthreads();
    for (int blk = 0; blk < 6; blk++) {
        float p = 0.0f;
        for (int i = t; i < HDIM; i += 256) p += fabsf(g_theta[blk * HDIM + i]);
        for (int o = 16; o > 0; o >>= 1) p += __shfl_xor_sync(0xffffffffu, p, o);
        if ((t & 31) == 0) atomicAdd(&ssum[blk], p);
    }
    __syncthreads();
    if (t == 0) {
        int best = 0;
        float bv = ssum[0];
        for (int b = 1; b < 6; b++) {
            if (ssum[b] > bv) { bv = ssum[b]; best = b; }
        }
        g_argmax = best;
    }
}

// h_new recomputed from fp32 g_P (same formulas as k_act -> bit-identical):
__global__ __launch_bounds__(256) void k_finalize(float* __restrict__ out) {
    size_t i = ((size_t)blockIdx.x * 256 + threadIdx.x) * 4;
    if (i >= BH) return;
    int m = g_argmax;
    size_t row = i >> 10;
    size_t h4 = i & 1023;
    float4 r;
    if (m == 4) {
        r = *(const float4*)(out + BH + i);
    } else if (m == 5) {
        float4 po = *(const float4*)(g_P + row * NROW4 + 3072 + h4);
        float4 cn = *(const float4*)(out + BH + i);
        r.x = sigmoid_f(po.x) * tanhf(cn.x);
        r.y = sigmoid_f(po.y) * tanhf(cn.y);
        r.z = sigmoid_f(po.z) * tanhf(cn.z);
        r.w = sigmoid_f(po.w) * tanhf(cn.w);
    } else {
        float4 p = *(const float4*)(g_P + row * NROW4 + (size_t)m * 1024 + h4);
        if (m == 2) {
            r.x = tanhf(p.x);
            r.y = tanhf(p.y);
            r.z = tanhf(p.z);
            r.w = tanhf(p.w);
        } else {
            r.x = sigmoid_f(p.x);
            r.y = sigmoid_f(p.y);
            r.z = sigmoid_f(p.z);
            r.w = sigmoid_f(p.w);
        }
    }
    *(float4*)(out + i) = r;
}

// ---------------------------------------------------------------------------
extern "C" void kernel_launch(void* const* d_in, const int* in_sizes, int n_in,
                              void* d_out, int out_size)
{
    const float* x      = (const float*)d_in[0];
    const float* hidden = (const float*)d_in[1];
    const float* cin    = (const float*)d_in[2];
    const float* mp     = (const float*)d_in[3];
    const float* Wf     = (const float*)d_in[4];
    const float* bf     = (const float*)d_in[5];
    const float* Uf     = (const float*)d_in[6];
    const float* Wi     = (const float*)d_in[7];
    const float* bi     = (const float*)d_in[8];
    const float* Ui     = (const float*)d_in[9];
    const float* Wc     = (const float*)d_in[10];
    const float* bc     = (const float*)d_in[11];
    const float* Uc     = (const float*)d_in[12];
    const float* Wo     = (const float*)d_in[13];
    const float* bo     = (const float*)d_in[14];
    const float* Uo     = (const float*)d_in[15];
    float* out = (float*)d_out;

    cudaFuncSetAttribute(k_gates_mma, cudaFuncAttributeMaxDynamicSharedMemorySize,
                         SMEM_NEED);

    k_prep_h<<<BSZ * HDIM / 4 / 256, 256>>>(hidden);
    k_prep_u<<<NROW4 * HDIM / 4 / 256, 256>>>(Uf, Ui, Uc, Uo);
    k_prep_aug<<<(BSZ + NROW4) / 256, 256>>>(x, Wf, Wi, Wc, Wo, bf, bi, bc, bo);

    dim3 gg(BSZ / 128, NROW4 / 128);
    k_gates_mma<<<gg, 128, SMEM_NEED>>>();
    k_act<<<BSZ * 256 / 256, 256>>>(cin, out);

    k_zero<<<(SIXH + 255) / 256, 256>>>();
    for (int it = 0; it < GD_ITERS; it++) {
        k_gd<<<592, 256>>>(mp);
        k_update<<<(SIXH + 255) / 256, 256>>>();
    }
    k_argmax<<<1, 256>>>();
    k_finalize<<<(int)(BH / 1024ULL), 256>>>(out);
}